// round 10
// baseline (speedup 1.0000x reference)
#include <cuda_runtime.h>
#include <cuda_bf16.h>
#include <cstdint>

#define NN_MAX 100000
#define NG_MAX 1024
#define D 128
#define NE_MAX 1600000

// ---------------- device scratch (allocation-free rule) ----------------
__device__ float4 g_x1  [NN_MAX * D / 4];
__device__ float4 g_x2  [NN_MAX * D / 4];
__device__ float4 g_pool[NG_MAX * D / 4];
// CSR
__device__ int g_deg [NN_MAX + 64];
__device__ int g_off [NN_MAX + 64];
__device__ int g_cur [NN_MAX + 64];
__device__ int g_esrc[NE_MAX];
__device__ int g_part [64];
__device__ int g_part2[64];
// weight images, fragment-major: per matrix 16384 u32 = [hi 8192][lo 8192]
__device__ uint32_t g_wtB[8][16384];
__device__ float g_st[8][2][128];     // [matrix][S/T][col]
__device__ int g_is64;

// ---------------- helpers ----------------
__device__ __forceinline__ int edge_idx(const void* ei, int i) {
    if (g_is64) return (int)((const long long*)ei)[i];
    return ((const int*)ei)[i];
}

__device__ __forceinline__ void mma16816(float* c, const uint32_t* a, const uint32_t* b) {
    asm volatile(
        "mma.sync.aligned.m16n8k16.row.col.f32.bf16.bf16.f32 "
        "{%0,%1,%2,%3}, {%4,%5,%6,%7}, {%8,%9}, {%0,%1,%2,%3};"
        : "+f"(c[0]), "+f"(c[1]), "+f"(c[2]), "+f"(c[3])
        : "r"(a[0]), "r"(a[1]), "r"(a[2]), "r"(a[3]), "r"(b[0]), "r"(b[1]));
}

__device__ __forceinline__ void ldm_x4(uint32_t& a0, uint32_t& a1, uint32_t& a2,
                                       uint32_t& a3, uint32_t addr) {
    asm volatile("ldmatrix.sync.aligned.m8n8.x4.shared.b16 {%0,%1,%2,%3}, [%4];"
                 : "=r"(a0), "=r"(a1), "=r"(a2), "=r"(a3) : "r"(addr));
}

__device__ __forceinline__ uint32_t smem_u32(const void* p) {
    uint32_t a;
    asm("{ .reg .u64 t; cvta.to.shared.u64 t, %1; cvt.u32.u64 %0, t; }"
        : "=r"(a) : "l"(p));
    return a;
}

__device__ __forceinline__ uint32_t pack_bf16_hi(float a, float b, uint32_t& lo) {
    __nv_bfloat16 h0 = __float2bfloat16(a);
    __nv_bfloat16 h1 = __float2bfloat16(b);
    __nv_bfloat16 l0 = __float2bfloat16(a - __bfloat162float(h0));
    __nv_bfloat16 l1 = __float2bfloat16(b - __bfloat162float(h1));
    lo = (uint32_t)__bfloat16_as_ushort(l0) | ((uint32_t)__bfloat16_as_ushort(l1) << 16);
    return (uint32_t)__bfloat16_as_ushort(h0) | ((uint32_t)__bfloat16_as_ushort(h1) << 16);
}

// ---------------- dtype detector ----------------
__global__ void detect_kernel(const int* __restrict__ ei32) {
    int any = 0;
    for (int i = threadIdx.x; i < 2048; i += 32)
        if (ei32[2 * i + 1] != 0) any = 1;
    any = __any_sync(0xffffffffu, any);
    if (threadIdx.x == 0) g_is64 = any ? 0 : 1;
}

// ---------------- zero kernels ----------------
__global__ void zero_f4(float4* __restrict__ p, int n4) {
    int i = blockIdx.x * blockDim.x + threadIdx.x;
    if (i < n4) p[i] = make_float4(0.f, 0.f, 0.f, 0.f);
}
__global__ void zero_i(int* __restrict__ p, int n) {
    int i = blockIdx.x * blockDim.x + threadIdx.x;
    if (i < n) p[i] = 0;
}

// ---------------- CSR build ----------------
__global__ void hist_kernel(const void* __restrict__ ei, int nE) {
    int e = blockIdx.x * blockDim.x + threadIdx.x;
    if (e >= nE) return;
    atomicAdd(&g_deg[edge_idx(ei, nE + e)], 1);
}

__global__ void scan_sum(int nN) {
    __shared__ int red[1024];
    int t = threadIdx.x;
    int base = blockIdx.x * 4096 + t * 4;
    int s = 0;
#pragma unroll
    for (int q = 0; q < 4; q++)
        if (base + q < nN) s += g_deg[base + q];
    red[t] = s; __syncthreads();
    for (int off = 512; off > 0; off >>= 1) {
        if (t < off) red[t] += red[t + off];
        __syncthreads();
    }
    if (t == 0) g_part[blockIdx.x] = red[0];
}

__global__ void scan_part(int nblk, int nN) {
    if (threadIdx.x == 0) {
        int run = 0;
        for (int i = 0; i < nblk; i++) { g_part2[i] = run; run += g_part[i]; }
        g_off[nN] = run;
    }
}

__global__ void scan_final(int nN) {
    __shared__ int sc[1024];
    int t = threadIdx.x;
    int base = blockIdx.x * 4096 + t * 4;
    int d[4]; int s = 0;
#pragma unroll
    for (int q = 0; q < 4; q++) {
        d[q] = (base + q < nN) ? g_deg[base + q] : 0;
        s += d[q];
    }
    sc[t] = s; __syncthreads();
    for (int off = 1; off < 1024; off <<= 1) {
        int v = (t >= off) ? sc[t - off] : 0;
        __syncthreads();
        sc[t] += v;
        __syncthreads();
    }
    int run = g_part2[blockIdx.x] + sc[t] - s;
#pragma unroll
    for (int q = 0; q < 4; q++) {
        if (base + q < nN) { g_off[base + q] = run; g_cur[base + q] = run; }
        run += d[q];
    }
}

__global__ void fill_kernel(const void* __restrict__ ei, int nE) {
    int e = blockIdx.x * blockDim.x + threadIdx.x;
    if (e >= nE) return;
    int src = edge_idx(ei, e);
    int dst = edge_idx(ei, nE + e);
    int slot = atomicAdd(&g_cur[dst], 1);
    g_esrc[slot] = src;
}

// ---------------- global pool ----------------
__global__ void pool_kernel(const float* __restrict__ x, const void* __restrict__ batch,
                            float* __restrict__ pool, int n) {
    int gid = blockIdx.x * blockDim.x + threadIdx.x;
    int node = gid >> 5, lane = gid & 31;
    if (node >= n) return;
    int g = edge_idx(batch, node);
    float4 v = ((const float4*)(x + (size_t)node * D))[lane];
    float* p = pool + (size_t)g * D + lane * 4;
    asm volatile("red.global.add.v4.f32 [%0], {%1,%2,%3,%4};"
                 :: "l"(p), "f"(v.x), "f"(v.y), "f"(v.z), "f"(v.w)
                 : "memory");
}

// ---------------- weight prep: fragment-major split-bf16 B image ----------------
__global__ void prep_b(const float* __restrict__ W1, const float* __restrict__ W2,
                       const float* __restrict__ hW1, const float* __restrict__ hW2) {
    int m = blockIdx.x;
    const float* src = (m < 3) ? (W1 + m * 16384)
                     : (m < 6) ? (W2 + (m - 3) * 16384)
                     : (m == 6 ? hW1 : hW2);
    uint32_t* dst = g_wtB[m];
    for (int idx = threadIdx.x; idx < 64 * 128; idx += 256) {
        int p = idx >> 7;         // kpair 0..63
        int n = idx & 127;        // col 0..127
        uint32_t lo;
        uint32_t hi = pack_bf16_hi(src[(2 * p) * 128 + n], src[(2 * p + 1) * 128 + n], lo);
        int nb = n >> 3, gB = n & 7;
        int ks = p >> 3, q = p & 7, tg = q & 3, kh = q >> 2;
        int lane = gB * 4 + tg;
        int fi = ((nb * 8 + ks) * 32 + lane) * 2 + kh;
        dst[fi] = hi;
        dst[8192 + fi] = lo;
    }
}

__global__ void prep_st(const float* __restrict__ b1, const float* __restrict__ gam,
                        const float* __restrict__ bet, const float* __restrict__ mu,
                        const float* __restrict__ var, const float* __restrict__ b2,
                        const float* __restrict__ hb1, const float* __restrict__ hb2) {
    int m = blockIdx.x, c = threadIdx.x;
    float S = 1.f, T;
    if (m < 3) {
        int i = m * 128 + c;
        S = gam[i] * rsqrtf(var[i] + 1e-5f);
        T = bet[i] + (b1[i] - mu[i]) * S;
    } else if (m < 6) T = b2[(m - 3) * 128 + c];
    else if (m == 6) T = hb1[c];
    else T = hb2[c];
    g_st[m][0][c] = S;
    g_st[m][1][c] = T;
}

// ---------------- fused layer kernel ----------------
// CTA: 128-row tile, 512 threads, 16 warps (warp tile 32x32).
// Phase A: stage A = x[row] (+ CSR gather sum) -> split bf16 smem (stride 68).
//          stage B1 + B2 weight images (fragment-major).
// Phase 1: mainloop over B1 -> Cr; epilogue1: relu(S1*acc+T1) -> rewrite A smem.
// Phase 2: mainloop over B2 -> Cr; epilogue2: S2*acc+T2 (opt relu) -> global C.
#define AH_OFF 0
#define AL_OFF 8704
#define B1_OFF 17408
#define B2_OFF 33792
#define SMEM_U32_TOT 50176
#define SMEM_BYTES (SMEM_U32_TOT * 4)

__device__ __forceinline__ void mainloop(const uint32_t* __restrict__ smB,
                                         uint32_t adrH0, uint32_t adrH1,
                                         uint32_t adrL0, uint32_t adrL1,
                                         int nq, int lane, float Cr[2][4][4]) {
#pragma unroll
    for (int i = 0; i < 2; i++)
#pragma unroll
        for (int j = 0; j < 4; j++)
#pragma unroll
            for (int q = 0; q < 4; q++) Cr[i][j][q] = 0.f;
    const uint2* BH2 = (const uint2*)smB;
    const uint2* BL2 = (const uint2*)(smB + 8192);
#pragma unroll 2
    for (int ks = 0; ks < 8; ks++) {
        uint32_t cb = ks * 32;
        uint32_t ah[2][4], al[2][4], bh[4][2], bl[4][2];
        ldm_x4(ah[0][0], ah[0][1], ah[0][2], ah[0][3], adrH0 + cb);
        ldm_x4(ah[1][0], ah[1][1], ah[1][2], ah[1][3], adrH1 + cb);
        ldm_x4(al[0][0], al[0][1], al[0][2], al[0][3], adrL0 + cb);
        ldm_x4(al[1][0], al[1][1], al[1][2], al[1][3], adrL1 + cb);
#pragma unroll
        for (int nf = 0; nf < 4; nf++) {
            int fi = ((nq * 4 + nf) * 8 + ks) * 32 + lane;
            uint2 h2 = BH2[fi];
            uint2 l2 = BL2[fi];
            bh[nf][0] = h2.x; bh[nf][1] = h2.y;
            bl[nf][0] = l2.x; bl[nf][1] = l2.y;
        }
#pragma unroll
        for (int mf = 0; mf < 2; mf++)
#pragma unroll
            for (int nf = 0; nf < 4; nf++) {
                mma16816(Cr[mf][nf], ah[mf], bh[nf]);
                mma16816(Cr[mf][nf], al[mf], bh[nf]);
                mma16816(Cr[mf][nf], ah[mf], bl[nf]);
            }
    }
}

template <bool GATHER, bool RELU2>
__global__ void __launch_bounds__(512)
fused_layer(const float* __restrict__ A,
            const uint32_t* __restrict__ img1, const uint32_t* __restrict__ img2,
            const float* __restrict__ s1S, const float* __restrict__ s1T,
            const float* __restrict__ s2S, const float* __restrict__ s2T,
            float* __restrict__ C, int M) {
    extern __shared__ __align__(16) uint32_t sm[];
    int tid = threadIdx.x;
    int row0 = blockIdx.x * 128;

    // stage both weight images (linear copies; L2-resident source)
    {
        const uint4* s1 = (const uint4*)img1;
        const uint4* s2 = (const uint4*)img2;
        uint4* d1 = (uint4*)(sm + B1_OFF);
        uint4* d2 = (uint4*)(sm + B2_OFF);
#pragma unroll
        for (int i = 0; i < 8; i++) {
            d1[tid + i * 512] = s1[tid + i * 512];
            d2[tid + i * 512] = s2[tid + i * 512];
        }
    }

    // stage A: thread -> row tid>>2, quarter tid&3 (32 floats = 8 float4)
    {
        int r = tid >> 2, cq = tid & 3;
        int gr = row0 + r;
        bool v = gr < M;
        float4 acc[8];
        if (v) {
            const float4* Ar = (const float4*)(A + (size_t)gr * D) + cq * 8;
#pragma unroll
            for (int j = 0; j < 8; j++) acc[j] = Ar[j];
            if (GATHER) {
                int b = __ldg(&g_off[gr]), e = __ldg(&g_off[gr + 1]);
                const float4* x4 = (const float4*)A;
                int j = b;
                for (; j + 1 < e; j += 2) {
                    const float4* p0 = x4 + (size_t)__ldg(&g_esrc[j]) * 32 + cq * 8;
                    const float4* p1 = x4 + (size_t)__ldg(&g_esrc[j + 1]) * 32 + cq * 8;
#pragma unroll
                    for (int q = 0; q < 8; q++) {
                        float4 u0 = p0[q], u1 = p1[q];
                        acc[q].x += u0.x + u1.x;
                        acc[q].y += u0.y + u1.y;
                        acc[q].z += u0.z + u1.z;
                        acc[q].w += u0.w + u1.w;
                    }
                }
                if (j < e) {
                    const float4* p0 = x4 + (size_t)__ldg(&g_esrc[j]) * 32 + cq * 8;
#pragma unroll
                    for (int q = 0; q < 8; q++) {
                        float4 u0 = p0[q];
                        acc[q].x += u0.x; acc[q].y += u0.y;
                        acc[q].z += u0.z; acc[q].w += u0.w;
                    }
                }
            }
        } else {
#pragma unroll
            for (int j = 0; j < 8; j++) acc[j] = make_float4(0.f, 0.f, 0.f, 0.f);
        }
        uint32_t hp[16], lp[16];
#pragma unroll
        for (int j = 0; j < 8; j++) {
            hp[2 * j]     = pack_bf16_hi(acc[j].x, acc[j].y, lp[2 * j]);
            hp[2 * j + 1] = pack_bf16_hi(acc[j].z, acc[j].w, lp[2 * j + 1]);
        }
        uint4* dH = (uint4*)(sm + AH_OFF + r * 68 + cq * 16);
        uint4* dL = (uint4*)(sm + AL_OFF + r * 68 + cq * 16);
#pragma unroll
        for (int t = 0; t < 4; t++) {
            dH[t] = make_uint4(hp[4 * t], hp[4 * t + 1], hp[4 * t + 2], hp[4 * t + 3]);
            dL[t] = make_uint4(lp[4 * t], lp[4 * t + 1], lp[4 * t + 2], lp[4 * t + 3]);
        }
    }
    __syncthreads();

    int lane = tid & 31, wid = tid >> 5;
    int g = lane >> 2, tg = lane & 3;
    int mq = wid & 3, nq = wid >> 2;

    uint32_t sbase = smem_u32(sm);
    uint32_t aRow = (uint32_t)(mq * 32 + (lane & 15));
    uint32_t aCol = (uint32_t)((lane >> 4) * 4);
    uint32_t adrH0 = sbase + (AH_OFF + aRow * 68 + aCol) * 4;
    uint32_t adrH1 = adrH0 + 16 * 68 * 4;
    uint32_t adrL0 = adrH0 + (AL_OFF - AH_OFF) * 4;
    uint32_t adrL1 = adrL0 + 16 * 68 * 4;

    float Cr[2][4][4];

    // ---- GEMM 1 ----
    mainloop(sm + B1_OFF, adrH0, adrH1, adrL0, adrL1, nq, lane, Cr);
    __syncthreads();   // everyone done reading A smem

    // epilogue 1: relu(S1*acc + T1) -> rewrite A smem (split bf16)
#pragma unroll
    for (int nf = 0; nf < 4; nf++) {
        int col = nq * 32 + nf * 8 + 2 * tg;
        float s0 = __ldg(s1S + col), s1v = __ldg(s1S + col + 1);
        float t0 = __ldg(s1T + col), t1v = __ldg(s1T + col + 1);
        int p = nq * 16 + nf * 4 + tg;   // kpair index
#pragma unroll
        for (int mf = 0; mf < 2; mf++)
#pragma unroll
            for (int hh = 0; hh < 2; hh++) {
                int rloc = mq * 32 + mf * 16 + g + hh * 8;
                float v0 = fmaxf(Cr[mf][nf][hh * 2 + 0] * s0 + t0, 0.f);
                float v1 = fmaxf(Cr[mf][nf][hh * 2 + 1] * s1v + t1v, 0.f);
                uint32_t lo;
                uint32_t hi = pack_bf16_hi(v0, v1, lo);
                sm[AH_OFF + rloc * 68 + p] = hi;
                sm[AL_OFF + rloc * 68 + p] = lo;
            }
    }
    __syncthreads();

    // ---- GEMM 2 ----
    mainloop(sm + B2_OFF, adrH0, adrH1, adrL0, adrL1, nq, lane, Cr);

    // epilogue 2 -> global
#pragma unroll
    for (int mf = 0; mf < 2; mf++)
#pragma unroll
        for (int nf = 0; nf < 4; nf++) {
            int col = nq * 32 + nf * 8 + 2 * tg;
            float s0 = __ldg(s2S + col), s1v = __ldg(s2S + col + 1);
            float t0 = __ldg(s2T + col), t1v = __ldg(s2T + col + 1);
#pragma unroll
            for (int hh = 0; hh < 2; hh++) {
                int row = row0 + mq * 32 + mf * 16 + g + hh * 8;
                if (row < M) {
                    float v0 = Cr[mf][nf][hh * 2 + 0] * s0 + t0;
                    float v1 = Cr[mf][nf][hh * 2 + 1] * s1v + t1v;
                    if (RELU2) { v0 = fmaxf(v0, 0.f); v1 = fmaxf(v1, 0.f); }
                    *(float2*)(C + (size_t)row * D + col) = make_float2(v0, v1);
                }
            }
        }
}

extern "C" void kernel_launch(void* const* d_in, const int* in_sizes, int n_in,
                              void* d_out, int out_size) {
    const float* x    = (const float*)d_in[0];
    const void* ei    = d_in[1];
    const void* batch = d_in[2];
    const float* W1   = (const float*)d_in[3];
    const float* b1   = (const float*)d_in[4];
    const float* gam  = (const float*)d_in[5];
    const float* bet  = (const float*)d_in[6];
    const float* mu   = (const float*)d_in[7];
    const float* var  = (const float*)d_in[8];
    const float* W2   = (const float*)d_in[9];
    const float* b2   = (const float*)d_in[10];
    const float* hW1  = (const float*)d_in[11];
    const float* hb1  = (const float*)d_in[12];
    const float* hW2  = (const float*)d_in[13];
    const float* hb2  = (const float*)d_in[14];
    float* out = (float*)d_out;

    int nN = in_sizes[0] / D;          // 100000
    int nE = in_sizes[1] / 2;          // 1600000
    int nG = out_size / D;             // 1024

    void* p;
    cudaGetSymbolAddress(&p, g_x1);   float* x1   = (float*)p;
    cudaGetSymbolAddress(&p, g_x2);   float* x2   = (float*)p;
    cudaGetSymbolAddress(&p, g_pool); float* pool = (float*)p;
    cudaGetSymbolAddress(&p, g_wtB);  uint32_t* wt = (uint32_t*)p;
    cudaGetSymbolAddress(&p, g_st);   float* st = (float*)p;
    cudaGetSymbolAddress(&p, g_deg);  int* deg = (int*)p;

    cudaFuncSetAttribute(fused_layer<true, true>,
                         cudaFuncAttributeMaxDynamicSharedMemorySize, SMEM_BYTES);
    cudaFuncSetAttribute(fused_layer<false, false>,
                         cudaFuncAttributeMaxDynamicSharedMemorySize, SMEM_BYTES);

    int edgeBlocks = (nE + 255) / 256;
    int scanBlocks = (nN + 4095) / 4096;
    int ggrid = (nN + 127) / 128;
    int hgrid = (nG + 127) / 128;

    detect_kernel<<<1, 32>>>((const int*)ei);
    prep_b<<<8, 256>>>(W1, W2, hW1, hW2);
    prep_st<<<8, 128>>>(b1, gam, bet, mu, var, b2, hb1, hb2);

    // CSR build
    zero_i<<<(nN + 1023) / 1024, 1024>>>(deg, nN);
    hist_kernel<<<edgeBlocks, 256>>>(ei, nE);
    scan_sum<<<scanBlocks, 1024>>>(nN);
    scan_part<<<1, 32>>>(scanBlocks, nN);
    scan_final<<<scanBlocks, 1024>>>(nN);
    fill_kernel<<<edgeBlocks, 256>>>(ei, nE);

    const float* xin = x;
    float* xbuf[2] = {x1, x2};
    for (int l = 0; l < 3; l++) {
        float* xo = xbuf[l & 1];
        fused_layer<true, true><<<ggrid, 512, SMEM_BYTES>>>(
            xin, wt + (size_t)l * 16384, wt + (size_t)(3 + l) * 16384,
            st + l * 256, st + l * 256 + 128,
            st + (3 + l) * 256, st + (3 + l) * 256 + 128,
            xo, nN);
        xin = xo;
    }

    zero_f4<<<(nG * 32 + 255) / 256, 256>>>((float4*)pool, nG * 32);
    pool_kernel<<<(nN * 32 + 255) / 256, 256>>>(xin, batch, pool, nN);

    fused_layer<false, false><<<hgrid, 512, SMEM_BYTES>>>(
        pool, wt + (size_t)6 * 16384, wt + (size_t)7 * 16384,
        st + 6 * 256, st + 6 * 256 + 128,
        st + 7 * 256, st + 7 * 256 + 128,
        out, nG);
}

// round 13
// speedup vs baseline: 2.1621x; 2.1621x over previous
#include <cuda_runtime.h>
#include <cuda_bf16.h>
#include <cstdint>

#define NN_MAX 100000
#define NG_MAX 1024
#define D 128
#define NE_MAX 1600000

// ---------------- device scratch (allocation-free rule) ----------------
__device__ float4 g_agg [NN_MAX * D / 4];
__device__ float4 g_x1  [NN_MAX * D / 4];
__device__ float4 g_x2  [NN_MAX * D / 4];
__device__ float4 g_pool[NG_MAX * D / 4];
// CSR
__device__ int g_deg [NN_MAX + 64];
__device__ int g_off [NN_MAX + 64];
__device__ int g_cur [NN_MAX + 64];
__device__ int g_esrc[NE_MAX];
__device__ int g_part [64];
__device__ int g_part2[64];
// weight images, fragment-major: per matrix 16384 u32 = [hi 8192][lo 8192]
__device__ uint32_t g_wtB[8][16384];
__device__ float g_st[8][2][128];     // [matrix][S/T][col]
__device__ int g_is64;

// ---------------- helpers ----------------
__device__ __forceinline__ int edge_idx(const void* ei, int i) {
    if (g_is64) return (int)((const long long*)ei)[i];
    return ((const int*)ei)[i];
}

__device__ __forceinline__ void mma16816(float* c, const uint32_t* a, const uint32_t* b) {
    asm volatile(
        "mma.sync.aligned.m16n8k16.row.col.f32.bf16.bf16.f32 "
        "{%0,%1,%2,%3}, {%4,%5,%6,%7}, {%8,%9}, {%0,%1,%2,%3};"
        : "+f"(c[0]), "+f"(c[1]), "+f"(c[2]), "+f"(c[3])
        : "r"(a[0]), "r"(a[1]), "r"(a[2]), "r"(a[3]), "r"(b[0]), "r"(b[1]));
}

__device__ __forceinline__ void ldm_x4(uint32_t& a0, uint32_t& a1, uint32_t& a2,
                                       uint32_t& a3, uint32_t addr) {
    asm volatile("ldmatrix.sync.aligned.m8n8.x4.shared.b16 {%0,%1,%2,%3}, [%4];"
                 : "=r"(a0), "=r"(a1), "=r"(a2), "=r"(a3) : "r"(addr));
}

__device__ __forceinline__ uint32_t smem_u32(const void* p) {
    uint32_t a;
    asm("{ .reg .u64 t; cvta.to.shared.u64 t, %1; cvt.u32.u64 %0, t; }"
        : "=r"(a) : "l"(p));
    return a;
}

__device__ __forceinline__ uint32_t pack_bf16_hi(float a, float b, uint32_t& lo) {
    __nv_bfloat16 h0 = __float2bfloat16(a);
    __nv_bfloat16 h1 = __float2bfloat16(b);
    __nv_bfloat16 l0 = __float2bfloat16(a - __bfloat162float(h0));
    __nv_bfloat16 l1 = __float2bfloat16(b - __bfloat162float(h1));
    lo = (uint32_t)__bfloat16_as_ushort(l0) | ((uint32_t)__bfloat16_as_ushort(l1) << 16);
    return (uint32_t)__bfloat16_as_ushort(h0) | ((uint32_t)__bfloat16_as_ushort(h1) << 16);
}

// ---------------- dtype detector ----------------
__global__ void detect_kernel(const int* __restrict__ ei32) {
    int any = 0;
    for (int i = threadIdx.x; i < 2048; i += 32)
        if (ei32[2 * i + 1] != 0) any = 1;
    any = __any_sync(0xffffffffu, any);
    if (threadIdx.x == 0) g_is64 = any ? 0 : 1;
}

// ---------------- zero kernels ----------------
__global__ void zero_f4(float4* __restrict__ p, int n4) {
    int i = blockIdx.x * blockDim.x + threadIdx.x;
    if (i < n4) p[i] = make_float4(0.f, 0.f, 0.f, 0.f);
}
__global__ void zero_i(int* __restrict__ p, int n) {
    int i = blockIdx.x * blockDim.x + threadIdx.x;
    if (i < n) p[i] = 0;
}

// ---------------- CSR build ----------------
__global__ void hist_kernel(const void* __restrict__ ei, int nE) {
    int e = blockIdx.x * blockDim.x + threadIdx.x;
    if (e >= nE) return;
    atomicAdd(&g_deg[edge_idx(ei, nE + e)], 1);
}

__global__ void scan_sum(int nN) {
    __shared__ int red[1024];
    int t = threadIdx.x;
    int base = blockIdx.x * 4096 + t * 4;
    int s = 0;
#pragma unroll
    for (int q = 0; q < 4; q++)
        if (base + q < nN) s += g_deg[base + q];
    red[t] = s; __syncthreads();
    for (int off = 512; off > 0; off >>= 1) {
        if (t < off) red[t] += red[t + off];
        __syncthreads();
    }
    if (t == 0) g_part[blockIdx.x] = red[0];
}

__global__ void scan_part(int nblk, int nN) {
    if (threadIdx.x == 0) {
        int run = 0;
        for (int i = 0; i < nblk; i++) { g_part2[i] = run; run += g_part[i]; }
        g_off[nN] = run;
    }
}

__global__ void scan_final(int nN) {
    __shared__ int sc[1024];
    int t = threadIdx.x;
    int base = blockIdx.x * 4096 + t * 4;
    int d[4]; int s = 0;
#pragma unroll
    for (int q = 0; q < 4; q++) {
        d[q] = (base + q < nN) ? g_deg[base + q] : 0;
        s += d[q];
    }
    sc[t] = s; __syncthreads();
    for (int off = 1; off < 1024; off <<= 1) {
        int v = (t >= off) ? sc[t - off] : 0;
        __syncthreads();
        sc[t] += v;
        __syncthreads();
    }
    int run = g_part2[blockIdx.x] + sc[t] - s;
#pragma unroll
    for (int q = 0; q < 4; q++) {
        if (base + q < nN) { g_off[base + q] = run; g_cur[base + q] = run; }
        run += d[q];
    }
}

__global__ void fill_kernel(const void* __restrict__ ei, int nE) {
    int e = blockIdx.x * blockDim.x + threadIdx.x;
    if (e >= nE) return;
    int src = edge_idx(ei, e);
    int dst = edge_idx(ei, nE + e);
    int slot = atomicAdd(&g_cur[dst], 1);
    g_esrc[slot] = src;
}

// ---------------- CSR gather (standalone: high occupancy hides L2 latency) ---------
__global__ void gather_kernel(const float* __restrict__ x, float* __restrict__ agg, int nN) {
    int wid = threadIdx.x >> 5, lane = threadIdx.x & 31;
    int node = blockIdx.x * 8 + wid;
    if (node >= nN) return;
    int b = g_off[node], e = g_off[node + 1];
    const float4* x4 = (const float4*)x;
    float4 a0 = make_float4(0.f, 0.f, 0.f, 0.f), a1 = a0, a2 = a0, a3 = a0;
    int j = b;
    for (; j + 3 < e; j += 4) {
        int s0 = g_esrc[j], s1 = g_esrc[j + 1], s2 = g_esrc[j + 2], s3 = g_esrc[j + 3];
        float4 v0 = x4[(size_t)s0 * 32 + lane];
        float4 v1 = x4[(size_t)s1 * 32 + lane];
        float4 v2 = x4[(size_t)s2 * 32 + lane];
        float4 v3 = x4[(size_t)s3 * 32 + lane];
        a0.x += v0.x; a0.y += v0.y; a0.z += v0.z; a0.w += v0.w;
        a1.x += v1.x; a1.y += v1.y; a1.z += v1.z; a1.w += v1.w;
        a2.x += v2.x; a2.y += v2.y; a2.z += v2.z; a2.w += v2.w;
        a3.x += v3.x; a3.y += v3.y; a3.z += v3.z; a3.w += v3.w;
    }
    for (; j < e; j++) {
        float4 v0 = x4[(size_t)g_esrc[j] * 32 + lane];
        a0.x += v0.x; a0.y += v0.y; a0.z += v0.z; a0.w += v0.w;
    }
    a0.x += a1.x + a2.x + a3.x;
    a0.y += a1.y + a2.y + a3.y;
    a0.z += a1.z + a2.z + a3.z;
    a0.w += a1.w + a2.w + a3.w;
    ((float4*)agg)[(size_t)node * 32 + lane] = a0;
}

// ---------------- weight prep: fragment-major split-bf16 B image ----------------
__global__ void prep_b(const float* __restrict__ W1, const float* __restrict__ W2,
                       const float* __restrict__ hW1, const float* __restrict__ hW2) {
    int m = blockIdx.x;
    const float* src = (m < 3) ? (W1 + m * 16384)
                     : (m < 6) ? (W2 + (m - 3) * 16384)
                     : (m == 6 ? hW1 : hW2);
    uint32_t* dst = g_wtB[m];
    for (int idx = threadIdx.x; idx < 64 * 128; idx += 256) {
        int p = idx >> 7;         // kpair 0..63
        int n = idx & 127;        // col 0..127
        uint32_t lo;
        uint32_t hi = pack_bf16_hi(src[(2 * p) * 128 + n], src[(2 * p + 1) * 128 + n], lo);
        int nb = n >> 3, gB = n & 7;
        int ks = p >> 3, q = p & 7, tg = q & 3, kh = q >> 2;
        int lane = gB * 4 + tg;
        int fi = ((nb * 8 + ks) * 32 + lane) * 2 + kh;
        dst[fi] = hi;
        dst[8192 + fi] = lo;
    }
}

__global__ void prep_st(const float* __restrict__ b1, const float* __restrict__ gam,
                        const float* __restrict__ bet, const float* __restrict__ mu,
                        const float* __restrict__ var, const float* __restrict__ b2,
                        const float* __restrict__ hb1, const float* __restrict__ hb2) {
    int m = blockIdx.x, c = threadIdx.x;
    float S = 1.f, T;
    if (m < 3) {
        int i = m * 128 + c;
        S = gam[i] * rsqrtf(var[i] + 1e-5f);
        T = bet[i] + (b1[i] - mu[i]) * S;
    } else if (m < 6) T = b2[(m - 3) * 128 + c];
    else if (m == 6) T = hb1[c];
    else T = hb2[c];
    g_st[m][0][c] = S;
    g_st[m][1][c] = T;
}

// ---------------- fused double-GEMM kernel ----------------
// CTA: 128-row tile, 512 threads, 16 warps (warp tile 32x32).
// A = x[row] (+ agg[row]) -> split bf16 smem. Both weight images staged.
// GEMM1 -> epilogue1 relu(S1*acc+T1) -> rewrite A smem -> GEMM2 -> epilogue2.
// OUT: 0 = relu -> C;  1 = relu -> red.add pool[batch[row]];  2 = plain -> C.
#define AH_OFF 0
#define AL_OFF 8704
#define B1_OFF 17408
#define B2_OFF 33792
#define SMEM_U32_TOT 50176
#define SMEM_BYTES (SMEM_U32_TOT * 4)

__device__ __forceinline__ void mainloop(const uint32_t* __restrict__ smB,
                                         uint32_t adrH0, uint32_t adrH1,
                                         uint32_t adrL0, uint32_t adrL1,
                                         int nq, int lane, float Cr[2][4][4]) {
#pragma unroll
    for (int i = 0; i < 2; i++)
#pragma unroll
        for (int j = 0; j < 4; j++)
#pragma unroll
            for (int q = 0; q < 4; q++) Cr[i][j][q] = 0.f;
    const uint2* BH2 = (const uint2*)smB;
    const uint2* BL2 = (const uint2*)(smB + 8192);
#pragma unroll 2
    for (int ks = 0; ks < 8; ks++) {
        uint32_t cb = ks * 32;
        uint32_t ah[2][4], al[2][4], bh[4][2], bl[4][2];
        ldm_x4(ah[0][0], ah[0][1], ah[0][2], ah[0][3], adrH0 + cb);
        ldm_x4(ah[1][0], ah[1][1], ah[1][2], ah[1][3], adrH1 + cb);
        ldm_x4(al[0][0], al[0][1], al[0][2], al[0][3], adrL0 + cb);
        ldm_x4(al[1][0], al[1][1], al[1][2], al[1][3], adrL1 + cb);
#pragma unroll
        for (int nf = 0; nf < 4; nf++) {
            int fi = ((nq * 4 + nf) * 8 + ks) * 32 + lane;
            uint2 h2 = BH2[fi];
            uint2 l2 = BL2[fi];
            bh[nf][0] = h2.x; bh[nf][1] = h2.y;
            bl[nf][0] = l2.x; bl[nf][1] = l2.y;
        }
#pragma unroll
        for (int mf = 0; mf < 2; mf++)
#pragma unroll
            for (int nf = 0; nf < 4; nf++) {
                mma16816(Cr[mf][nf], ah[mf], bh[nf]);
                mma16816(Cr[mf][nf], al[mf], bh[nf]);
                mma16816(Cr[mf][nf], ah[mf], bl[nf]);
            }
    }
}

template <int OUT>
__global__ void __launch_bounds__(512)
fused_gemm(const float* __restrict__ A, const float* __restrict__ A2,
           const uint32_t* __restrict__ img1, const uint32_t* __restrict__ img2,
           const float* __restrict__ s1S, const float* __restrict__ s1T,
           const float* __restrict__ s2S, const float* __restrict__ s2T,
           float* __restrict__ C, const void* __restrict__ batch,
           float* __restrict__ pool, int M) {
    extern __shared__ __align__(16) uint32_t sm[];
    int tid = threadIdx.x;
    int row0 = blockIdx.x * 128;

    // stage both weight images (linear copies; L2-resident source)
    {
        const uint4* s1 = (const uint4*)img1;
        const uint4* s2 = (const uint4*)img2;
        uint4* d1 = (uint4*)(sm + B1_OFF);
        uint4* d2 = (uint4*)(sm + B2_OFF);
#pragma unroll
        for (int i = 0; i < 8; i++) {
            d1[tid + i * 512] = s1[tid + i * 512];
            d2[tid + i * 512] = s2[tid + i * 512];
        }
    }

    // stage A: thread -> row tid>>2, quarter tid&3 (32 floats)
    {
        int r = tid >> 2, cq = tid & 3;
        int gr = row0 + r;
        bool v = gr < M;
        float4 acc[8];
        if (v) {
            const float4* Ar = (const float4*)(A + (size_t)gr * D) + cq * 8;
#pragma unroll
            for (int j = 0; j < 8; j++) acc[j] = Ar[j];
            if (A2) {
                const float4* A2r = (const float4*)(A2 + (size_t)gr * D) + cq * 8;
#pragma unroll
                for (int j = 0; j < 8; j++) {
                    float4 u = A2r[j];
                    acc[j].x += u.x; acc[j].y += u.y;
                    acc[j].z += u.z; acc[j].w += u.w;
                }
            }
        } else {
#pragma unroll
            for (int j = 0; j < 8; j++) acc[j] = make_float4(0.f, 0.f, 0.f, 0.f);
        }
        uint32_t hp[16], lp[16];
#pragma unroll
        for (int j = 0; j < 8; j++) {
            hp[2 * j]     = pack_bf16_hi(acc[j].x, acc[j].y, lp[2 * j]);
            hp[2 * j + 1] = pack_bf16_hi(acc[j].z, acc[j].w, lp[2 * j + 1]);
        }
        uint4* dH = (uint4*)(sm + AH_OFF + r * 68 + cq * 16);
        uint4* dL = (uint4*)(sm + AL_OFF + r * 68 + cq * 16);
#pragma unroll
        for (int t = 0; t < 4; t++) {
            dH[t] = make_uint4(hp[4 * t], hp[4 * t + 1], hp[4 * t + 2], hp[4 * t + 3]);
            dL[t] = make_uint4(lp[4 * t], lp[4 * t + 1], lp[4 * t + 2], lp[4 * t + 3]);
        }
    }
    __syncthreads();

    int lane = tid & 31, wid = tid >> 5;
    int g = lane >> 2, tg = lane & 3;
    int mq = wid & 3, nq = wid >> 2;

    uint32_t sbase = smem_u32(sm);
    uint32_t aRow = (uint32_t)(mq * 32 + (lane & 15));
    uint32_t aCol = (uint32_t)((lane >> 4) * 4);
    uint32_t adrH0 = sbase + (AH_OFF + aRow * 68 + aCol) * 4;
    uint32_t adrH1 = adrH0 + 16 * 68 * 4;
    uint32_t adrL0 = adrH0 + (AL_OFF - AH_OFF) * 4;
    uint32_t adrL1 = adrL0 + 16 * 68 * 4;

    float Cr[2][4][4];

    // ---- GEMM 1 ----
    mainloop(sm + B1_OFF, adrH0, adrH1, adrL0, adrL1, nq, lane, Cr);
    __syncthreads();

    // epilogue 1: relu(S1*acc + T1) -> rewrite A smem (split bf16)
#pragma unroll
    for (int nf = 0; nf < 4; nf++) {
        int col = nq * 32 + nf * 8 + 2 * tg;
        float s0 = __ldg(s1S + col), s1v = __ldg(s1S + col + 1);
        float t0 = __ldg(s1T + col), t1v = __ldg(s1T + col + 1);
        int p = nq * 16 + nf * 4 + tg;   // kpair index
#pragma unroll
        for (int mf = 0; mf < 2; mf++)
#pragma unroll
            for (int hh = 0; hh < 2; hh++) {
                int rloc = mq * 32 + mf * 16 + g + hh * 8;
                float v0 = fmaxf(Cr[mf][nf][hh * 2 + 0] * s0 + t0, 0.f);
                float v1 = fmaxf(Cr[mf][nf][hh * 2 + 1] * s1v + t1v, 0.f);
                uint32_t lo;
                uint32_t hi = pack_bf16_hi(v0, v1, lo);
                sm[AH_OFF + rloc * 68 + p] = hi;
                sm[AL_OFF + rloc * 68 + p] = lo;
            }
    }
    __syncthreads();

    // ---- GEMM 2 ----
    mainloop(sm + B2_OFF, adrH0, adrH1, adrL0, adrL1, nq, lane, Cr);

    // epilogue 2
#pragma unroll
    for (int mf = 0; mf < 2; mf++)
#pragma unroll
        for (int nf = 0; nf < 4; nf++) {
            int col = nq * 32 + nf * 8 + 2 * tg;
            float s0 = __ldg(s2S + col), s1v = __ldg(s2S + col + 1);
            float t0 = __ldg(s2T + col), t1v = __ldg(s2T + col + 1);
#pragma unroll
            for (int hh = 0; hh < 2; hh++) {
                int row = row0 + mq * 32 + mf * 16 + g + hh * 8;
                if (row < M) {
                    float v0 = Cr[mf][nf][hh * 2 + 0] * s0 + t0;
                    float v1 = Cr[mf][nf][hh * 2 + 1] * s1v + t1v;
                    if (OUT != 2) { v0 = fmaxf(v0, 0.f); v1 = fmaxf(v1, 0.f); }
                    if (OUT == 1) {
                        int gb = edge_idx(batch, row);
                        float* pp = pool + (size_t)gb * D + col;
                        asm volatile("red.global.add.v2.f32 [%0], {%1,%2};"
                                     :: "l"(pp), "f"(v0), "f"(v1) : "memory");
                    } else {
                        *(float2*)(C + (size_t)row * D + col) = make_float2(v0, v1);
                    }
                }
            }
        }
}

extern "C" void kernel_launch(void* const* d_in, const int* in_sizes, int n_in,
                              void* d_out, int out_size) {
    const float* x    = (const float*)d_in[0];
    const void* ei    = d_in[1];
    const void* batch = d_in[2];
    const float* W1   = (const float*)d_in[3];
    const float* b1   = (const float*)d_in[4];
    const float* gam  = (const float*)d_in[5];
    const float* bet  = (const float*)d_in[6];
    const float* mu   = (const float*)d_in[7];
    const float* var  = (const float*)d_in[8];
    const float* W2   = (const float*)d_in[9];
    const float* b2   = (const float*)d_in[10];
    const float* hW1  = (const float*)d_in[11];
    const float* hb1  = (const float*)d_in[12];
    const float* hW2  = (const float*)d_in[13];
    const float* hb2  = (const float*)d_in[14];
    float* out = (float*)d_out;

    int nN = in_sizes[0] / D;          // 100000
    int nE = in_sizes[1] / 2;          // 1600000
    int nG = out_size / D;             // 1024

    void* p;
    cudaGetSymbolAddress(&p, g_agg);  float* agg  = (float*)p;
    cudaGetSymbolAddress(&p, g_x1);   float* x1   = (float*)p;
    cudaGetSymbolAddress(&p, g_x2);   float* x2   = (float*)p;
    cudaGetSymbolAddress(&p, g_pool); float* pool = (float*)p;
    cudaGetSymbolAddress(&p, g_wtB);  uint32_t* wt = (uint32_t*)p;
    cudaGetSymbolAddress(&p, g_st);   float* st = (float*)p;
    cudaGetSymbolAddress(&p, g_deg);  int* deg = (int*)p;

    cudaFuncSetAttribute(fused_gemm<0>, cudaFuncAttributeMaxDynamicSharedMemorySize, SMEM_BYTES);
    cudaFuncSetAttribute(fused_gemm<1>, cudaFuncAttributeMaxDynamicSharedMemorySize, SMEM_BYTES);
    cudaFuncSetAttribute(fused_gemm<2>, cudaFuncAttributeMaxDynamicSharedMemorySize, SMEM_BYTES);

    int edgeBlocks = (nE + 255) / 256;
    int scanBlocks = (nN + 4095) / 4096;
    int ggrid = (nN + 127) / 128;
    int hgrid = (nG + 127) / 128;

    detect_kernel<<<1, 32>>>((const int*)ei);
    prep_b<<<8, 256>>>(W1, W2, hW1, hW2);
    prep_st<<<8, 128>>>(b1, gam, bet, mu, var, b2, hb1, hb2);

    // CSR build
    zero_i<<<(nN + 1023) / 1024, 1024>>>(deg, nN);
    hist_kernel<<<edgeBlocks, 256>>>(ei, nE);
    scan_sum<<<scanBlocks, 1024>>>(nN);
    scan_part<<<1, 32>>>(scanBlocks, nN);
    scan_final<<<scanBlocks, 1024>>>(nN);
    fill_kernel<<<edgeBlocks, 256>>>(ei, nE);

    // pool cleared early (layer-3 epilogue red-adds into it)
    zero_f4<<<(nG * 32 + 255) / 256, 256>>>((float4*)pool, nG * 32);

    const float* xin = x;
    float* xbuf[2] = {x1, x2};
    for (int l = 0; l < 3; l++) {
        gather_kernel<<<(nN + 7) / 8, 256>>>(xin, agg, nN);
        float* xo = xbuf[l & 1];
        if (l < 2) {
            fused_gemm<0><<<ggrid, 512, SMEM_BYTES>>>(
                xin, agg, wt + (size_t)l * 16384, wt + (size_t)(3 + l) * 16384,
                st + l * 256, st + l * 256 + 128,
                st + (3 + l) * 256, st + (3 + l) * 256 + 128,
                xo, nullptr, nullptr, nN);
            xin = xo;
        } else {
            fused_gemm<1><<<ggrid, 512, SMEM_BYTES>>>(
                xin, agg, wt + (size_t)l * 16384, wt + (size_t)(3 + l) * 16384,
                st + l * 256, st + l * 256 + 128,
                st + (3 + l) * 256, st + (3 + l) * 256 + 128,
                nullptr, batch, pool, nN);
        }
    }

    // head: Linear->ReLU->Linear fused
    fused_gemm<2><<<hgrid, 512, SMEM_BYTES>>>(
        pool, nullptr, wt + (size_t)6 * 16384, wt + (size_t)7 * 16384,
        st + 6 * 256, st + 6 * 256 + 128,
        st + 7 * 256, st + 7 * 256 + 128,
        out, nullptr, nullptr, nG);
}

// round 16
// speedup vs baseline: 2.7581x; 1.2757x over previous
#include <cuda_runtime.h>
#include <cuda_bf16.h>
#include <cstdint>

#define NN_MAX 100000
#define NG_MAX 1024
#define D 128
#define NE_MAX 1600000

// ---------------- device scratch (allocation-free rule) ----------------
__device__ float4 g_agg [NN_MAX * D / 4];
__device__ float4 g_x1  [NN_MAX * D / 4];
__device__ float4 g_x2  [NN_MAX * D / 4];
__device__ float4 g_pool[NG_MAX * D / 4];
// CSR
__device__ int g_deg [NN_MAX + 64];
__device__ int g_off [NN_MAX + 64];
__device__ int g_cur [NN_MAX + 64];
__device__ int g_esrc[NE_MAX];
__device__ int g_part [64];
__device__ int g_part2[64];
// weight images, fragment-major: per matrix 16384 u32 = [hi 8192][lo 8192]
__device__ __align__(16) uint32_t g_wtB[8][16384];
__device__ float g_st[8][2][128];     // [matrix][S/T][col]
__device__ int g_is64;

// ---------------- helpers ----------------
__device__ __forceinline__ int edge_idx(const void* ei, int i) {
    if (g_is64) return (int)((const long long*)ei)[i];
    return ((const int*)ei)[i];
}

__device__ __forceinline__ void mma16816(float* c, const uint32_t* a, const uint32_t* b) {
    asm volatile(
        "mma.sync.aligned.m16n8k16.row.col.f32.bf16.bf16.f32 "
        "{%0,%1,%2,%3}, {%4,%5,%6,%7}, {%8,%9}, {%0,%1,%2,%3};"
        : "+f"(c[0]), "+f"(c[1]), "+f"(c[2]), "+f"(c[3])
        : "r"(a[0]), "r"(a[1]), "r"(a[2]), "r"(a[3]), "r"(b[0]), "r"(b[1]));
}

__device__ __forceinline__ void ldm_x4(uint32_t& a0, uint32_t& a1, uint32_t& a2,
                                       uint32_t& a3, uint32_t addr) {
    asm volatile("ldmatrix.sync.aligned.m8n8.x4.shared.b16 {%0,%1,%2,%3}, [%4];"
                 : "=r"(a0), "=r"(a1), "=r"(a2), "=r"(a3) : "r"(addr));
}

__device__ __forceinline__ uint32_t smem_u32(const void* p) {
    uint32_t a;
    asm("{ .reg .u64 t; cvta.to.shared.u64 t, %1; cvt.u32.u64 %0, t; }"
        : "=r"(a) : "l"(p));
    return a;
}

__device__ __forceinline__ uint32_t pack_bf16_hi(float a, float b, uint32_t& lo) {
    __nv_bfloat16 h0 = __float2bfloat16(a);
    __nv_bfloat16 h1 = __float2bfloat16(b);
    __nv_bfloat16 l0 = __float2bfloat16(a - __bfloat162float(h0));
    __nv_bfloat16 l1 = __float2bfloat16(b - __bfloat162float(h1));
    lo = (uint32_t)__bfloat16_as_ushort(l0) | ((uint32_t)__bfloat16_as_ushort(l1) << 16);
    return (uint32_t)__bfloat16_as_ushort(h0) | ((uint32_t)__bfloat16_as_ushort(h1) << 16);
}

// ---------------- dtype detector ----------------
__global__ void detect_kernel(const int* __restrict__ ei32) {
    int any = 0;
    for (int i = threadIdx.x; i < 2048; i += 32)
        if (ei32[2 * i + 1] != 0) any = 1;
    any = __any_sync(0xffffffffu, any);
    if (threadIdx.x == 0) g_is64 = any ? 0 : 1;
}

// ---------------- zero kernels ----------------
__global__ void zero_f4(float4* __restrict__ p, int n4) {
    int i = blockIdx.x * blockDim.x + threadIdx.x;
    if (i < n4) p[i] = make_float4(0.f, 0.f, 0.f, 0.f);
}
__global__ void zero_i(int* __restrict__ p, int n) {
    int i = blockIdx.x * blockDim.x + threadIdx.x;
    if (i < n) p[i] = 0;
}

// ---------------- CSR build ----------------
__global__ void hist_kernel(const void* __restrict__ ei, int nE) {
    int e = blockIdx.x * blockDim.x + threadIdx.x;
    if (e >= nE) return;
    atomicAdd(&g_deg[edge_idx(ei, nE + e)], 1);
}

__global__ void scan_sum(int nN) {
    __shared__ int red[1024];
    int t = threadIdx.x;
    int base = blockIdx.x * 4096 + t * 4;
    int s = 0;
#pragma unroll
    for (int q = 0; q < 4; q++)
        if (base + q < nN) s += g_deg[base + q];
    red[t] = s; __syncthreads();
    for (int off = 512; off > 0; off >>= 1) {
        if (t < off) red[t] += red[t + off];
        __syncthreads();
    }
    if (t == 0) g_part[blockIdx.x] = red[0];
}

__global__ void scan_part(int nblk, int nN) {
    if (threadIdx.x == 0) {
        int run = 0;
        for (int i = 0; i < nblk; i++) { g_part2[i] = run; run += g_part[i]; }
        g_off[nN] = run;
    }
}

__global__ void scan_final(int nN) {
    __shared__ int sc[1024];
    int t = threadIdx.x;
    int base = blockIdx.x * 4096 + t * 4;
    int d[4]; int s = 0;
#pragma unroll
    for (int q = 0; q < 4; q++) {
        d[q] = (base + q < nN) ? g_deg[base + q] : 0;
        s += d[q];
    }
    sc[t] = s; __syncthreads();
    for (int off = 1; off < 1024; off <<= 1) {
        int v = (t >= off) ? sc[t - off] : 0;
        __syncthreads();
        sc[t] += v;
        __syncthreads();
    }
    int run = g_part2[blockIdx.x] + sc[t] - s;
#pragma unroll
    for (int q = 0; q < 4; q++) {
        if (base + q < nN) { g_off[base + q] = run; g_cur[base + q] = run; }
        run += d[q];
    }
}

__global__ void fill_kernel(const void* __restrict__ ei, int nE) {
    int e = blockIdx.x * blockDim.x + threadIdx.x;
    if (e >= nE) return;
    int src = edge_idx(ei, e);
    int dst = edge_idx(ei, nE + e);
    int slot = atomicAdd(&g_cur[dst], 1);
    g_esrc[slot] = src;
}

// ---------------- CSR gather: agg[n] = x[n] + sum_{j in adj(n)} x[src_j] ----------
__global__ void gather_kernel(const float* __restrict__ x, float* __restrict__ agg, int nN) {
    int wid = threadIdx.x >> 5, lane = threadIdx.x & 31;
    int node = blockIdx.x * 8 + wid;
    if (node >= nN) return;
    int b = g_off[node], e = g_off[node + 1];
    const float4* x4 = (const float4*)x;
    float4 a0 = x4[(size_t)node * 32 + lane];   // self term (GIN eps=0)
    float4 a1 = make_float4(0.f, 0.f, 0.f, 0.f), a2 = a1, a3 = a1;
    int j = b;
    for (; j + 3 < e; j += 4) {
        int s0 = g_esrc[j], s1 = g_esrc[j + 1], s2 = g_esrc[j + 2], s3 = g_esrc[j + 3];
        float4 v0 = x4[(size_t)s0 * 32 + lane];
        float4 v1 = x4[(size_t)s1 * 32 + lane];
        float4 v2 = x4[(size_t)s2 * 32 + lane];
        float4 v3 = x4[(size_t)s3 * 32 + lane];
        a0.x += v0.x; a0.y += v0.y; a0.z += v0.z; a0.w += v0.w;
        a1.x += v1.x; a1.y += v1.y; a1.z += v1.z; a1.w += v1.w;
        a2.x += v2.x; a2.y += v2.y; a2.z += v2.z; a2.w += v2.w;
        a3.x += v3.x; a3.y += v3.y; a3.z += v3.z; a3.w += v3.w;
    }
    for (; j < e; j++) {
        float4 v0 = x4[(size_t)g_esrc[j] * 32 + lane];
        a0.x += v0.x; a0.y += v0.y; a0.z += v0.z; a0.w += v0.w;
    }
    a0.x += a1.x + a2.x + a3.x;
    a0.y += a1.y + a2.y + a3.y;
    a0.z += a1.z + a2.z + a3.z;
    a0.w += a1.w + a2.w + a3.w;
    ((float4*)agg)[(size_t)node * 32 + lane] = a0;
}

// ---------------- weight prep: fragment-major split-bf16 B image ----------------
__global__ void prep_b(const float* __restrict__ W1, const float* __restrict__ W2,
                       const float* __restrict__ hW1, const float* __restrict__ hW2) {
    int m = blockIdx.x;
    const float* src = (m < 3) ? (W1 + m * 16384)
                     : (m < 6) ? (W2 + (m - 3) * 16384)
                     : (m == 6 ? hW1 : hW2);
    uint32_t* dst = g_wtB[m];
    for (int idx = threadIdx.x; idx < 64 * 128; idx += 256) {
        int p = idx >> 7;         // kpair 0..63
        int n = idx & 127;        // col 0..127
        uint32_t lo;
        uint32_t hi = pack_bf16_hi(src[(2 * p) * 128 + n], src[(2 * p + 1) * 128 + n], lo);
        int nb = n >> 3, gB = n & 7;
        int ks = p >> 3, q = p & 7, tg = q & 3, kh = q >> 2;
        int lane = gB * 4 + tg;
        int fi = ((nb * 8 + ks) * 32 + lane) * 2 + kh;
        dst[fi] = hi;
        dst[8192 + fi] = lo;
    }
}

__global__ void prep_st(const float* __restrict__ b1, const float* __restrict__ gam,
                        const float* __restrict__ bet, const float* __restrict__ mu,
                        const float* __restrict__ var, const float* __restrict__ b2,
                        const float* __restrict__ hb1, const float* __restrict__ hb2) {
    int m = blockIdx.x, c = threadIdx.x;
    float S = 1.f, T;
    if (m < 3) {
        int i = m * 128 + c;
        S = gam[i] * rsqrtf(var[i] + 1e-5f);
        T = bet[i] + (b1[i] - mu[i]) * S;
    } else if (m < 6) T = b2[(m - 3) * 128 + c];
    else if (m == 6) T = hb1[c];
    else T = hb2[c];
    g_st[m][0][c] = S;
    g_st[m][1][c] = T;
}

// ---------------- fused double-GEMM kernel (64 rows / 256 thr / 35 KB smem) -------
// 8 warps, warp tile 32x32 (mq=wid&1, nq=wid>>1). A split-bf16 in static smem.
// B fragments loaded straight from the global fragment-major image (L1/L2-resident).
// GEMM1 -> epi1 relu(S1*acc+T1) rewrites A smem -> GEMM2 -> epi2.
// OUT: 0 = relu -> C;  1 = relu -> red.add pool[batch[row]];  2 = plain -> C.
#define AROWS 64
#define AL_OFF (AROWS * 68)     // u32 offset of lo buffer

__device__ __forceinline__ void mainloop_g(const uint32_t* __restrict__ img,
                                           uint32_t adrH0, uint32_t adrH1,
                                           uint32_t adrL0, uint32_t adrL1,
                                           int nq, int lane, float Cr[2][4][4]) {
#pragma unroll
    for (int i = 0; i < 2; i++)
#pragma unroll
        for (int j = 0; j < 4; j++)
#pragma unroll
            for (int q = 0; q < 4; q++) Cr[i][j][q] = 0.f;
    const uint2* BH2 = (const uint2*)img;
    const uint2* BL2 = (const uint2*)(img + 8192);
#pragma unroll 2
    for (int ks = 0; ks < 8; ks++) {
        uint32_t cb = ks * 32;
        uint32_t ah[2][4], al[2][4], bh[4][2], bl[4][2];
        // issue B global loads first (independent; L1-hit after first warp)
#pragma unroll
        for (int nf = 0; nf < 4; nf++) {
            int fi = ((nq * 4 + nf) * 8 + ks) * 32 + lane;
            uint2 h2 = __ldg(&BH2[fi]);
            uint2 l2 = __ldg(&BL2[fi]);
            bh[nf][0] = h2.x; bh[nf][1] = h2.y;
            bl[nf][0] = l2.x; bl[nf][1] = l2.y;
        }
        ldm_x4(ah[0][0], ah[0][1], ah[0][2], ah[0][3], adrH0 + cb);
        ldm_x4(ah[1][0], ah[1][1], ah[1][2], ah[1][3], adrH1 + cb);
        ldm_x4(al[0][0], al[0][1], al[0][2], al[0][3], adrL0 + cb);
        ldm_x4(al[1][0], al[1][1], al[1][2], al[1][3], adrL1 + cb);
#pragma unroll
        for (int mf = 0; mf < 2; mf++)
#pragma unroll
            for (int nf = 0; nf < 4; nf++) {
                mma16816(Cr[mf][nf], ah[mf], bh[nf]);
                mma16816(Cr[mf][nf], al[mf], bh[nf]);
                mma16816(Cr[mf][nf], ah[mf], bl[nf]);
            }
    }
}

template <int OUT>
__global__ void __launch_bounds__(256, 2)
fused_gemm(const float* __restrict__ A,
           const uint32_t* __restrict__ img1, const uint32_t* __restrict__ img2,
           const float* __restrict__ s1S, const float* __restrict__ s1T,
           const float* __restrict__ s2S, const float* __restrict__ s2T,
           float* __restrict__ C, const void* __restrict__ batch,
           float* __restrict__ pool, int M) {
    __shared__ __align__(16) uint32_t sm[AROWS * 68 * 2];   // hi + lo, 34.8 KB
    int tid = threadIdx.x;
    int row0 = blockIdx.x * AROWS;

    // stage A: thread -> row tid>>2, quarter tid&3 (32 floats)
    {
        int r = tid >> 2, cq = tid & 3;
        int gr = row0 + r;
        bool v = gr < M;
        float4 acc[8];
        if (v) {
            const float4* Ar = (const float4*)(A + (size_t)gr * D) + cq * 8;
#pragma unroll
            for (int j = 0; j < 8; j++) acc[j] = Ar[j];
        } else {
#pragma unroll
            for (int j = 0; j < 8; j++) acc[j] = make_float4(0.f, 0.f, 0.f, 0.f);
        }
        uint32_t hp[16], lp[16];
#pragma unroll
        for (int j = 0; j < 8; j++) {
            hp[2 * j]     = pack_bf16_hi(acc[j].x, acc[j].y, lp[2 * j]);
            hp[2 * j + 1] = pack_bf16_hi(acc[j].z, acc[j].w, lp[2 * j + 1]);
        }
        uint4* dH = (uint4*)(sm + r * 68 + cq * 16);
        uint4* dL = (uint4*)(sm + AL_OFF + r * 68 + cq * 16);
#pragma unroll
        for (int t = 0; t < 4; t++) {
            dH[t] = make_uint4(hp[4 * t], hp[4 * t + 1], hp[4 * t + 2], hp[4 * t + 3]);
            dL[t] = make_uint4(lp[4 * t], lp[4 * t + 1], lp[4 * t + 2], lp[4 * t + 3]);
        }
    }
    __syncthreads();

    int lane = tid & 31, wid = tid >> 5;
    int g = lane >> 2, tg = lane & 3;
    int mq = wid & 1, nq = wid >> 1;

    uint32_t sbase = smem_u32(sm);
    uint32_t aRow = (uint32_t)(mq * 32 + (lane & 15));
    uint32_t aCol = (uint32_t)((lane >> 4) * 4);
    uint32_t adrH0 = sbase + (aRow * 68 + aCol) * 4;
    uint32_t adrH1 = adrH0 + 16 * 68 * 4;
    uint32_t adrL0 = adrH0 + AL_OFF * 4;
    uint32_t adrL1 = adrL0 + 16 * 68 * 4;

    float Cr[2][4][4];

    // ---- GEMM 1 ----
    mainloop_g(img1, adrH0, adrH1, adrL0, adrL1, nq, lane, Cr);
    __syncthreads();

    // epilogue 1: relu(S1*acc + T1) -> rewrite A smem (split bf16)
#pragma unroll
    for (int nf = 0; nf < 4; nf++) {
        int col = nq * 32 + nf * 8 + 2 * tg;
        float s0 = __ldg(s1S + col), s1v = __ldg(s1S + col + 1);
        float t0 = __ldg(s1T + col), t1v = __ldg(s1T + col + 1);
        int p = nq * 16 + nf * 4 + tg;   // kpair index
#pragma unroll
        for (int mf = 0; mf < 2; mf++)
#pragma unroll
            for (int hh = 0; hh < 2; hh++) {
                int rloc = mq * 32 + mf * 16 + g + hh * 8;
                float v0 = fmaxf(Cr[mf][nf][hh * 2 + 0] * s0 + t0, 0.f);
                float v1 = fmaxf(Cr[mf][nf][hh * 2 + 1] * s1v + t1v, 0.f);
                uint32_t lo;
                uint32_t hi = pack_bf16_hi(v0, v1, lo);
                sm[rloc * 68 + p] = hi;
                sm[AL_OFF + rloc * 68 + p] = lo;
            }
    }
    __syncthreads();

    // ---- GEMM 2 ----
    mainloop_g(img2, adrH0, adrH1, adrL0, adrL1, nq, lane, Cr);

    // epilogue 2
#pragma unroll
    for (int mf = 0; mf < 2; mf++)
#pragma unroll
        for (int nf = 0; nf < 4; nf++) {
            int col = nq * 32 + nf * 8 + 2 * tg;
            float s0 = __ldg(s2S + col), s1v = __ldg(s2S + col + 1);
            float t0 = __ldg(s2T + col), t1v = __ldg(s2T + col + 1);
#pragma unroll
            for (int hh = 0; hh < 2; hh++) {
                int row = row0 + mq * 32 + mf * 16 + g + hh * 8;
                if (row < M) {
                    float v0 = Cr[mf][nf][hh * 2 + 0] * s0 + t0;
                    float v1 = Cr[mf][nf][hh * 2 + 1] * s1v + t1v;
                    if (OUT != 2) { v0 = fmaxf(v0, 0.f); v1 = fmaxf(v1, 0.f); }
                    if (OUT == 1) {
                        int gb = edge_idx(batch, row);
                        float* pp = pool + (size_t)gb * D + col;
                        asm volatile("red.global.add.v2.f32 [%0], {%1,%2};"
                                     :: "l"(pp), "f"(v0), "f"(v1) : "memory");
                    } else {
                        *(float2*)(C + (size_t)row * D + col) = make_float2(v0, v1);
                    }
                }
            }
        }
}

extern "C" void kernel_launch(void* const* d_in, const int* in_sizes, int n_in,
                              void* d_out, int out_size) {
    const float* x    = (const float*)d_in[0];
    const void* ei    = d_in[1];
    const void* batch = d_in[2];
    const float* W1   = (const float*)d_in[3];
    const float* b1   = (const float*)d_in[4];
    const float* gam  = (const float*)d_in[5];
    const float* bet  = (const float*)d_in[6];
    const float* mu   = (const float*)d_in[7];
    const float* var  = (const float*)d_in[8];
    const float* W2   = (const float*)d_in[9];
    const float* b2   = (const float*)d_in[10];
    const float* hW1  = (const float*)d_in[11];
    const float* hb1  = (const float*)d_in[12];
    const float* hW2  = (const float*)d_in[13];
    const float* hb2  = (const float*)d_in[14];
    float* out = (float*)d_out;

    int nN = in_sizes[0] / D;          // 100000
    int nE = in_sizes[1] / 2;          // 1600000
    int nG = out_size / D;             // 1024

    void* p;
    cudaGetSymbolAddress(&p, g_agg);  float* agg  = (float*)p;
    cudaGetSymbolAddress(&p, g_x1);   float* x1   = (float*)p;
    cudaGetSymbolAddress(&p, g_x2);   float* x2   = (float*)p;
    cudaGetSymbolAddress(&p, g_pool); float* pool = (float*)p;
    cudaGetSymbolAddress(&p, g_wtB);  uint32_t* wt = (uint32_t*)p;
    cudaGetSymbolAddress(&p, g_st);   float* st = (float*)p;
    cudaGetSymbolAddress(&p, g_deg);  int* deg = (int*)p;

    int edgeBlocks = (nE + 255) / 256;
    int scanBlocks = (nN + 4095) / 4096;
    int ggrid = (nN + AROWS - 1) / AROWS;
    int hgrid = (nG + AROWS - 1) / AROWS;

    detect_kernel<<<1, 32>>>((const int*)ei);
    prep_b<<<8, 256>>>(W1, W2, hW1, hW2);
    prep_st<<<8, 128>>>(b1, gam, bet, mu, var, b2, hb1, hb2);

    // CSR build
    zero_i<<<(nN + 1023) / 1024, 1024>>>(deg, nN);
    hist_kernel<<<edgeBlocks, 256>>>(ei, nE);
    scan_sum<<<scanBlocks, 1024>>>(nN);
    scan_part<<<1, 32>>>(scanBlocks, nN);
    scan_final<<<scanBlocks, 1024>>>(nN);
    fill_kernel<<<edgeBlocks, 256>>>(ei, nE);

    // pool cleared early (layer-3 epilogue red-adds into it)
    zero_f4<<<(nG * 32 + 255) / 256, 256>>>((float4*)pool, nG * 32);

    const float* xin = x;
    float* xbuf[2] = {x1, x2};
    for (int l = 0; l < 3; l++) {
        gather_kernel<<<(nN + 7) / 8, 256>>>(xin, agg, nN);
        float* xo = xbuf[l & 1];
        if (l < 2) {
            fused_gemm<0><<<ggrid, 256>>>(
                agg, wt + (size_t)l * 16384, wt + (size_t)(3 + l) * 16384,
                st + l * 256, st + l * 256 + 128,
                st + (3 + l) * 256, st + (3 + l) * 256 + 128,
                xo, nullptr, nullptr, nN);
            xin = xo;
        } else {
            fused_gemm<1><<<ggrid, 256>>>(
                agg, wt + (size_t)l * 16384, wt + (size_t)(3 + l) * 16384,
                st + l * 256, st + l * 256 + 128,
                st + (3 + l) * 256, st + (3 + l) * 256 + 128,
                nullptr, batch, pool, nN);
        }
    }

    // head: Linear->ReLU->Linear fused
    fused_gemm<2><<<hgrid, 256>>>(
        pool, wt + (size_t)6 * 16384, wt + (size_t)7 * 16384,
        st + 6 * 256, st + 6 * 256 + 128,
        st + 7 * 256, st + 7 * 256 + 128,
        out, nullptr, nullptr, nG);
}